// round 14
// baseline (speedup 1.0000x reference)
#include <cuda_runtime.h>
#include <cstdint>
#include <math.h>

// Problem shape (fixed by setup_inputs)
#define BB   8
#define HH   256
#define WW   256
#define NPIX (BB * HH * WW)
#define GRID 592          // 148 SMs x 4 blocks, all co-resident (one wave)
#define TPB  256
#define P1B  64           // mask-builder blocks (8 per batch)
#define WPB  66           // workers per batch (66*4 >= 256)
#define RPB  4            // max rows per worker block

// Persistent scratch. Counters/flags reset by the finalizer each launch.
__device__ unsigned g_mask[BB * 8 * WW];  // fg bitmask: [b][rowchunk][col]
__device__ int      g_nonempty[BB];
__device__ unsigned g_cnt[BB];            // per-batch mask-ready counters
__device__ unsigned g_done;               // completion ticket
__device__ double   g_part[GRID * 5];     // per-block partial sums

__device__ __forceinline__ float warp_sum_f(float v) {
    #pragma unroll
    for (int o = 16; o > 0; o >>= 1) v += __shfl_xor_sync(0xffffffffu, v, o);
    return v;
}

__device__ __forceinline__ float sqrt_approx(float x) {
    float r;
    asm("sqrt.approx.f32 %0, %1;" : "=f"(r) : "f"(x));
    return r;
}

__global__ void __launch_bounds__(TPB, 4)
fused_loss_kernel(const float* __restrict__ logits,
                  const float* __restrict__ target,
                  float* __restrict__ out, int out_size)
{
    const int tid  = threadIdx.x;
    const int bid  = blockIdx.x;
    const int lane = tid & 31, warp = tid >> 5;

    __shared__ float    s_g2[RPB][WW];
    __shared__ float    s_red[8][5];
    __shared__ unsigned s_ticket;

    // worker row assignment: never crosses a batch boundary
    const int wrk   = bid - P1B;                     // 0..527 for workers
    const int wb    = (wrk >= 0) ? (wrk / WPB) : 0;  // batch
    const int widx  = (wrk >= 0) ? (wrk - wb * WPB) : 0;
    const int r0    = widx * RPB;                    // row within batch
    const int nrows = (wrk >= 0) ? max(0, min(RPB, HH - r0)) : 0;
    const int grow0 = wb * HH + r0;                  // global row

    float ps[RPB];
    float acc0 = 0.f, acc1 = 0.f, acc2 = 0.f, acc3 = 0.f, acc4 = 0.f;

    if (bid < P1B) {
        // ========= mask builders: load 32 rows, pack, store, release ========
        int b   = bid >> 3;
        int col = ((bid & 7) << 5) + lane;
        int rc0 = warp << 5;
        const float* tp = target + b * HH * WW + col;

        unsigned mask = 0;
        #pragma unroll
        for (int i = 0; i < 32; i++) {
            float tv = tp[(rc0 + i) * WW];           // 32 independent loads
            if (tv > 0.5f) mask |= (1u << i);
        }
        g_mask[(b * 8 + warp) * WW + col] = mask;    // coalesced
        if (__any_sync(0xffffffffu, mask != 0u) && lane == 0)
            g_nonempty[b] = 1;                       // benign same-value race
        __threadfence();                             // release masks
        __syncthreads();
        if (tid == 0) atomicAdd(&g_cnt[b], 1u);
    } else if (nrows > 0) {
        // ========= workers: elementwise piece first (overlaps builders) =====
        float xs[RPB], ts[RPB];
        #pragma unroll
        for (int i = 0; i < RPB; i++) {
            if (i < nrows) {
                int idx = (grow0 + i) * WW + tid;
                xs[i] = logits[idx];
                ts[i] = target[idx];
            }
        }
        #pragma unroll
        for (int i = 0; i < RPB; i++) {
            if (i < nrows) {
                float x = xs[i];
                float t = fminf(fmaxf(ts[i], 0.0f), 1.0f);
                float th;
                asm("tanh.approx.f32 %0, %1;" : "=f"(th) : "f"(0.5f * x));
                float h = 0.5f * th;                 // sigmoid(x) = 0.5 + h
                float p = fminf(fmaxf(0.5f + h, 1e-6f), 1.0f - 1e-6f);
                float r = 0.5f + fabsf(h);           // sigmoid(|x|)
                // log1p(e^{-|x|}) = -ln(sigmoid(|x|)) = -ln2*log2(r)
                float ce = fmaxf(x, 0.0f) - 0.69314718055994531f * __log2f(r)
                         - x * t;
                ps[i] = p;
                acc0 += ce; acc1 += p; acc2 += t; acc3 += p * t;
            }
        }

        // ========= acquire this batch's masks (usually already ready) =======
        if (tid == 0) {
            volatile unsigned* vc = &g_cnt[wb];
            while (*vc < 8u) __nanosleep(32);
        }
        __syncthreads();
        __threadfence();

        // load this column's 8 mask words (coalesced, L2-hot)
        unsigned m[8];
        #pragma unroll
        for (int wp = 0; wp < 8; wp++)
            m[wp] = g_mask[(wb * 8 + wp) * WW + tid];

        // ========= vertical distances (exact reference semantics) ==========
        int fwdA[RPB], bwdA[RPB];
        {
            int r = r0, w = r >> 5, bit = r & 31;
            int best_lo = -513;
            #pragma unroll
            for (int wp = 0; wp < 8; wp++) {
                unsigned mm = m[wp];
                if (wp > w) mm = 0;
                else if (wp == w) mm &= (0xffffffffu >> (31 - bit));
                if (mm) best_lo = (wp << 5) + 31 - __clz(mm);
            }
            int f = r - best_lo;
            fwdA[0] = f;
            #pragma unroll
            for (int i = 1; i < RPB; i++) {
                if (i < nrows) {
                    int rr = r0 + i;
                    f = ((m[rr >> 5] >> (rr & 31)) & 1u) ? 0 : f + 1;
                    fwdA[i] = f;
                }
            }
        }
        {
            int re = r0 + nrows - 1, w = re >> 5, bit = re & 31;
            int best_hi = 768;
            #pragma unroll
            for (int wp = 7; wp >= 0; wp--) {
                unsigned mm = m[wp];
                if (wp < w) mm = 0;
                else if (wp == w) mm &= (0xffffffffu << bit);
                if (mm) best_hi = (wp << 5) + __ffs(mm) - 1;
            }
            int bw = best_hi - re;
            bwdA[nrows - 1] = bw;
            #pragma unroll
            for (int i = RPB - 2; i >= 0; i--) {
                if (i < nrows - 1) {
                    int rr = r0 + i;
                    bw = ((m[rr >> 5] >> (rr & 31)) & 1u) ? 0 : bw + 1;
                    bwdA[i] = bw;
                }
            }
        }

        float g2s[RPB];
        #pragma unroll
        for (int i = 0; i < RPB; i++) {
            if (i < nrows) {
                int g = min(fwdA[i], bwdA[i]);
                g2s[i] = (float)(g * g);
                s_g2[i][tid] = g2s[i];
            }
        }
        __syncthreads();

        // ========= exact horizontal EDT + boundary term =====================
        // Branch-free offsets 1..4 (clamped indices give candidates that are
        // provably >= the true minimum, so exactness is preserved); rare
        // warp-uniform tail for lanes needing a wider search.
        if (g_nonempty[wb]) {
            #pragma unroll
            for (int i = 0; i < RPB; i++) {
                if (i < nrows) {
                    float best = g2s[i];
                    #pragma unroll
                    for (int off = 1; off <= 4; off++) {
                        int l = tid - off; l = (l < 0) ? 0 : l;
                        int r = tid + off; r = (r > WW - 1) ? WW - 1 : r;
                        float cand = fminf(s_g2[i][l], s_g2[i][r])
                                   + (float)(off * off);
                        best = fminf(best, cand);
                    }
                    if (__any_sync(0xffffffffu, 25.0f < best)) {
                        int off = 5;
                        float o2 = 25.0f;
                        while (__any_sync(0xffffffffu, o2 < best)) {
                            int l = tid - off; l = (l < 0) ? 0 : l;
                            int r = tid + off; r = (r > WW - 1) ? WW - 1 : r;
                            best = fminf(best,
                                         fminf(s_g2[i][l], s_g2[i][r]) + o2);
                            off++;
                            o2 = (float)(off * off);
                            if (off >= WW) break;   // all columns covered
                        }
                    }
                    float dt = (best <= 1.0f) ? best : sqrt_approx(best);
                    acc4 += ps[i] * dt;
                }
            }
        }
    }

    // ========== per-block reduction -> g_part (deterministic) ===============
    {
        float accs[5] = { acc0, acc1, acc2, acc3, acc4 };
        #pragma unroll
        for (int s = 0; s < 5; s++) {
            float v = warp_sum_f(accs[s]);
            if (lane == 0) s_red[warp][s] = v;
        }
        __syncthreads();
        if (warp < 5) {                  // warps 0..4 reduce one scalar each
            float v = (lane < 8) ? s_red[lane][warp] : 0.0f;
            v = warp_sum_f(v);
            if (lane == 0) g_part[bid * 5 + warp] = (double)v;
        }
    }
    __threadfence();
    __syncthreads();

    // ========== completion ticket; last block finalizes =====================
    if (tid == 0) s_ticket = atomicAdd(&g_done, 1u);
    __syncthreads();

    if (s_ticket == GRID - 1) {
        __threadfence();
        double v0 = 0, v1 = 0, v2 = 0, v3 = 0, v4 = 0;
        for (int i = tid; i < GRID; i += TPB) {
            v0 += g_part[i * 5 + 0];
            v1 += g_part[i * 5 + 1];
            v2 += g_part[i * 5 + 2];
            v3 += g_part[i * 5 + 3];
            v4 += g_part[i * 5 + 4];
        }
        #pragma unroll
        for (int o = 16; o > 0; o >>= 1) {
            v0 += __shfl_xor_sync(0xffffffffu, v0, o);
            v1 += __shfl_xor_sync(0xffffffffu, v1, o);
            v2 += __shfl_xor_sync(0xffffffffu, v2, o);
            v3 += __shfl_xor_sync(0xffffffffu, v3, o);
            v4 += __shfl_xor_sync(0xffffffffu, v4, o);
        }
        __shared__ double s_d[TPB / 32][5];
        if (lane == 0) {
            s_d[warp][0] = v0; s_d[warp][1] = v1; s_d[warp][2] = v2;
            s_d[warp][3] = v3; s_d[warp][4] = v4;
        }
        __syncthreads();
        if (tid == 0) {
            double fsum[5] = {0, 0, 0, 0, 0};
            for (int w = 0; w < TPB / 32; w++)
                for (int s = 0; s < 5; s++) fsum[s] += s_d[w][s];

            const double N = (double)NPIX, S = 1e-6;
            double ce       = fsum[0] / N;
            double dice     = 1.0 - (2.0 * fsum[3] + S) / (fsum[1] + fsum[2] + S);
            double boundary = fsum[4] / N;
            double total    = ce + dice + 0.1 * boundary;

            float vals[4] = { (float)total, (float)ce, (float)dice, (float)boundary };
            for (int i = 0; i < out_size && i < 4; i++) out[i] = vals[i];

            // reset persistent state for next graph replay
            g_done = 0;
            for (int b = 0; b < BB; b++) { g_nonempty[b] = 0; g_cnt[b] = 0; }
        }
    }
}

extern "C" void kernel_launch(void* const* d_in, const int* in_sizes, int n_in,
                              void* d_out, int out_size) {
    const float* logits = (const float*)d_in[0];
    const float* target = (const float*)d_in[1];
    (void)in_sizes; (void)n_in;
    fused_loss_kernel<<<GRID, TPB>>>(logits, target, (float*)d_out, out_size);
}

// round 15
// speedup vs baseline: 1.0152x; 1.0152x over previous
#include <cuda_runtime.h>
#include <cstdint>
#include <math.h>

// Problem shape (fixed by setup_inputs)
#define BB   8
#define HH   256
#define WW   256
#define NPIX (BB * HH * WW)
#define GRID 576          // 64 builders + 512 workers; <= 592 co-resident
#define TPB  256
#define P1B  64           // mask-builder blocks (8 per batch)
#define WPB  64           // workers per batch (64*4 = 256 rows exactly)
#define RPB  4            // rows per worker block (always full)
#define PAD  8            // smem row padding for clamp-free EDT window

// Persistent scratch. Counters/flags reset by the finalizer each launch.
__device__ unsigned g_mask[BB * 8 * WW];  // fg bitmask: [b][rowchunk][col]
__device__ int      g_nonempty[BB];
__device__ unsigned g_cnt[BB];            // per-batch mask-ready counters
__device__ unsigned g_done;               // completion ticket
__device__ double   g_part[GRID * 5];     // per-block partial sums

__device__ __forceinline__ float warp_sum_f(float v) {
    #pragma unroll
    for (int o = 16; o > 0; o >>= 1) v += __shfl_xor_sync(0xffffffffu, v, o);
    return v;
}

__device__ __forceinline__ float sqrt_approx(float x) {
    float r;
    asm("sqrt.approx.f32 %0, %1;" : "=f"(r) : "f"(x));
    return r;
}

__global__ void __launch_bounds__(TPB, 4)
fused_loss_kernel(const float* __restrict__ logits,
                  const float* __restrict__ target,
                  float* __restrict__ out, int out_size)
{
    const int tid  = threadIdx.x;
    const int bid  = blockIdx.x;
    const int lane = tid & 31, warp = tid >> 5;

    __shared__ float    s_g2[RPB][WW + 2 * PAD];  // padded, clamp-free window
    __shared__ float    s_p[RPB][WW];
    __shared__ float    s_red[8][5];
    __shared__ unsigned s_ticket;

    // worker assignment (never crosses a batch boundary)
    const int wrk   = bid - P1B;                     // 0..511 for workers
    const int wb    = (wrk >= 0) ? (wrk >> 6) : 0;   // batch
    const int widx  = (wrk >= 0) ? (wrk & 63) : 0;
    const int r0    = widx * RPB;                    // row within batch
    const int grow0 = wb * HH + r0;                  // global row

    // row-major pixel mapping for elementwise + EDT phases
    const int rloc = tid >> 6;                       // 0..3
    const int c0   = (tid & 63) * 4;                 // column group

    float acc0 = 0.f, acc1 = 0.f, acc2 = 0.f, acc3 = 0.f, acc4 = 0.f;

    if (bid < P1B) {
        // ========= mask builders: load 32 rows, pack, store, release ========
        int b   = bid >> 3;
        int col = ((bid & 7) << 5) + lane;
        int rc0 = warp << 5;
        const float* tp = target + b * HH * WW + col;

        unsigned mask = 0;
        #pragma unroll
        for (int i = 0; i < 32; i++) {
            float tv = tp[(rc0 + i) * WW];           // 32 independent loads
            if (tv > 0.5f) mask |= (1u << i);
        }
        g_mask[(b * 8 + warp) * WW + col] = mask;    // coalesced
        if (__any_sync(0xffffffffu, mask != 0u) && lane == 0)
            g_nonempty[b] = 1;                       // benign same-value race
        __threadfence();                             // release masks
        __syncthreads();
        if (tid == 0) atomicAdd(&g_cnt[b], 1u);
    } else {
        // ========= workers: elementwise (float4, row-major) =================
        // INF pads for the EDT window (written once, before the sync below)
        if (tid < PAD) {
            #pragma unroll
            for (int i = 0; i < RPB; i++) {
                s_g2[i][tid] = 1e30f;
                s_g2[i][WW + PAD + tid] = 1e30f;
            }
        }

        const int idx4 = (grow0 + rloc) * WW + c0;
        float4 xv = *reinterpret_cast<const float4*>(logits + idx4);
        float4 tv = *reinterpret_cast<const float4*>(target + idx4);

        float pv[4];
        {
            const float xs[4] = { xv.x, xv.y, xv.z, xv.w };
            const float ts[4] = { tv.x, tv.y, tv.z, tv.w };
            #pragma unroll
            for (int k = 0; k < 4; k++) {
                float x = xs[k];
                float t = fminf(fmaxf(ts[k], 0.0f), 1.0f);
                float th;
                asm("tanh.approx.f32 %0, %1;" : "=f"(th) : "f"(0.5f * x));
                float h = 0.5f * th;                 // sigmoid(x) = 0.5 + h
                float p = fminf(fmaxf(0.5f + h, 1e-6f), 1.0f - 1e-6f);
                float r = 0.5f + fabsf(h);           // sigmoid(|x|)
                float ce = fmaxf(x, 0.0f) - 0.69314718055994531f * __log2f(r)
                         - x * t;
                pv[k] = p;
                acc0 += ce; acc1 += p; acc2 += t; acc3 += p * t;
            }
        }
        *reinterpret_cast<float4*>(&s_p[rloc][c0]) =
            make_float4(pv[0], pv[1], pv[2], pv[3]);

        // ========= acquire this batch's masks (usually already ready) =======
        if (tid == 0) {
            volatile unsigned* vc = &g_cnt[wb];
            while (*vc < 8u) __nanosleep(32);
        }
        __syncthreads();
        __threadfence();

        // ========= vertical distances (col-major: thread = column tid) ======
        {
            unsigned m[8];
            #pragma unroll
            for (int wp = 0; wp < 8; wp++)
                m[wp] = g_mask[(wb * 8 + wp) * WW + tid];

            int fwdA[RPB], bwdA[RPB];
            {
                int r = r0, w = r >> 5, bit = r & 31;
                int best_lo = -513;
                #pragma unroll
                for (int wp = 0; wp < 8; wp++) {
                    unsigned mm = m[wp];
                    if (wp > w) mm = 0;
                    else if (wp == w) mm &= (0xffffffffu >> (31 - bit));
                    if (mm) best_lo = (wp << 5) + 31 - __clz(mm);
                }
                int f = r - best_lo;
                fwdA[0] = f;
                #pragma unroll
                for (int i = 1; i < RPB; i++) {
                    int rr = r0 + i;
                    f = ((m[rr >> 5] >> (rr & 31)) & 1u) ? 0 : f + 1;
                    fwdA[i] = f;
                }
            }
            {
                int re = r0 + RPB - 1, w = re >> 5, bit = re & 31;
                int best_hi = 768;
                #pragma unroll
                for (int wp = 7; wp >= 0; wp--) {
                    unsigned mm = m[wp];
                    if (wp < w) mm = 0;
                    else if (wp == w) mm &= (0xffffffffu << bit);
                    if (mm) best_hi = (wp << 5) + __ffs(mm) - 1;
                }
                int bw = best_hi - re;
                bwdA[RPB - 1] = bw;
                #pragma unroll
                for (int i = RPB - 2; i >= 0; i--) {
                    int rr = r0 + i;
                    bw = ((m[rr >> 5] >> (rr & 31)) & 1u) ? 0 : bw + 1;
                    bwdA[i] = bw;
                }
            }
            #pragma unroll
            for (int i = 0; i < RPB; i++) {
                int g = min(fwdA[i], bwdA[i]);
                s_g2[i][PAD + tid] = (float)(g * g);
            }
        }
        __syncthreads();

        // ========= EDT (row-major: thread = 4 cols of 1 row) ================
        if (g_nonempty[wb]) {
            const float* row = &s_g2[rloc][0];
            // window cols c0-4 .. c0+7  ->  padded idx PAD+c0-4 (16B aligned)
            float v[12];
            {
                const float4 a = *reinterpret_cast<const float4*>(row + PAD + c0 - 4);
                const float4 b = *reinterpret_cast<const float4*>(row + PAD + c0);
                const float4 c = *reinterpret_cast<const float4*>(row + PAD + c0 + 4);
                v[0]=a.x; v[1]=a.y; v[2]=a.z; v[3]=a.w;
                v[4]=b.x; v[5]=b.y; v[6]=b.z; v[7]=b.w;
                v[8]=c.x; v[9]=c.y; v[10]=c.z; v[11]=c.w;
            }
            float best[4], bmax = 0.0f;
            #pragma unroll
            for (int k = 0; k < 4; k++) {
                float bk = v[4 + k];
                #pragma unroll
                for (int off = 1; off <= 4; off++) {
                    bk = fminf(bk, fminf(v[4 + k - off], v[4 + k + off])
                                   + (float)(off * off));
                }
                best[k] = bk;
                bmax = fmaxf(bmax, bk);
            }
            // rare warp-uniform wide search
            if (__any_sync(0xffffffffu, 25.0f < bmax)) {
                int off = 5;
                float o2 = 25.0f;
                while (__any_sync(0xffffffffu, o2 < bmax)) {
                    bmax = 0.0f;
                    #pragma unroll
                    for (int k = 0; k < 4; k++) {
                        int cc = c0 + k;
                        int l = cc - off; l = (l < 0) ? 0 : l;
                        int r = cc + off; r = (r > WW - 1) ? WW - 1 : r;
                        best[k] = fminf(best[k],
                                        fminf(row[PAD + l], row[PAD + r]) + o2);
                        bmax = fmaxf(bmax, best[k]);
                    }
                    off++;
                    o2 = (float)(off * off);
                    if (off >= WW) break;
                }
            }
            const float4 pq = *reinterpret_cast<const float4*>(&s_p[rloc][c0]);
            const float pk[4] = { pq.x, pq.y, pq.z, pq.w };
            #pragma unroll
            for (int k = 0; k < 4; k++) {
                float b2 = best[k];
                float dt = (b2 <= 1.0f) ? b2 : sqrt_approx(b2);
                acc4 += pk[k] * dt;
            }
        }
    }

    // ========== per-block reduction -> g_part (deterministic) ===============
    {
        float accs[5] = { acc0, acc1, acc2, acc3, acc4 };
        #pragma unroll
        for (int s = 0; s < 5; s++) {
            float v = warp_sum_f(accs[s]);
            if (lane == 0) s_red[warp][s] = v;
        }
        __syncthreads();
        if (warp < 5) {                  // warps 0..4 reduce one scalar each
            float v = (lane < 8) ? s_red[lane][warp] : 0.0f;
            v = warp_sum_f(v);
            if (lane == 0) g_part[bid * 5 + warp] = (double)v;
        }
    }
    __threadfence();
    __syncthreads();

    // ========== completion ticket; last block finalizes =====================
    if (tid == 0) s_ticket = atomicAdd(&g_done, 1u);
    __syncthreads();

    if (s_ticket == GRID - 1) {
        __threadfence();
        double v0 = 0, v1 = 0, v2 = 0, v3 = 0, v4 = 0;
        for (int i = tid; i < GRID; i += TPB) {
            v0 += g_part[i * 5 + 0];
            v1 += g_part[i * 5 + 1];
            v2 += g_part[i * 5 + 2];
            v3 += g_part[i * 5 + 3];
            v4 += g_part[i * 5 + 4];
        }
        #pragma unroll
        for (int o = 16; o > 0; o >>= 1) {
            v0 += __shfl_xor_sync(0xffffffffu, v0, o);
            v1 += __shfl_xor_sync(0xffffffffu, v1, o);
            v2 += __shfl_xor_sync(0xffffffffu, v2, o);
            v3 += __shfl_xor_sync(0xffffffffu, v3, o);
            v4 += __shfl_xor_sync(0xffffffffu, v4, o);
        }
        __shared__ double s_d[TPB / 32][5];
        if (lane == 0) {
            s_d[warp][0] = v0; s_d[warp][1] = v1; s_d[warp][2] = v2;
            s_d[warp][3] = v3; s_d[warp][4] = v4;
        }
        __syncthreads();
        if (tid == 0) {
            double fsum[5] = {0, 0, 0, 0, 0};
            for (int w = 0; w < TPB / 32; w++)
                for (int s = 0; s < 5; s++) fsum[s] += s_d[w][s];

            const double N = (double)NPIX, S = 1e-6;
            double ce       = fsum[0] / N;
            double dice     = 1.0 - (2.0 * fsum[3] + S) / (fsum[1] + fsum[2] + S);
            double boundary = fsum[4] / N;
            double total    = ce + dice + 0.1 * boundary;

            float vals[4] = { (float)total, (float)ce, (float)dice, (float)boundary };
            for (int i = 0; i < out_size && i < 4; i++) out[i] = vals[i];

            // reset persistent state for next graph replay
            g_done = 0;
            for (int b = 0; b < BB; b++) { g_nonempty[b] = 0; g_cnt[b] = 0; }
        }
    }
}

extern "C" void kernel_launch(void* const* d_in, const int* in_sizes, int n_in,
                              void* d_out, int out_size) {
    const float* logits = (const float*)d_in[0];
    const float* target = (const float*)d_in[1];
    (void)in_sizes; (void)n_in;
    fused_loss_kernel<<<GRID, TPB>>>(logits, target, (float*)d_out, out_size);
}

// round 16
// speedup vs baseline: 1.1552x; 1.1379x over previous
#include <cuda_runtime.h>
#include <cstdint>
#include <math.h>

// Problem shape (fixed by setup_inputs)
#define BB   8
#define HH   256
#define WW   256
#define NPIX (BB * HH * WW)
#define GRID 576          // 64 builders + 512 workers; <= 592 co-resident
#define TPB  256
#define P1B  64           // mask-builder blocks (8 per batch)
#define RPB  4            // rows per worker block (always full)
#define PAD  8            // smem row padding for clamp-free EDT window

// Persistent scratch. Counters/sums reset by the finalizer each launch.
__device__ unsigned g_mask[BB * 8 * WW];  // fg bitmask: [b][rowchunk][col]
__device__ int      g_nonempty[BB];
__device__ unsigned g_cnt[BB];            // per-batch mask-ready counters
__device__ unsigned g_done;               // completion ticket
__device__ double   g_sums[5];            // global sums (double atomics)

__device__ __forceinline__ float warp_sum_f(float v) {
    #pragma unroll
    for (int o = 16; o > 0; o >>= 1) v += __shfl_xor_sync(0xffffffffu, v, o);
    return v;
}

__device__ __forceinline__ float sqrt_approx(float x) {
    float r;
    asm("sqrt.approx.f32 %0, %1;" : "=f"(r) : "f"(x));
    return r;
}

__device__ __forceinline__ unsigned ld_acq_u32(const unsigned* p) {
    unsigned v;
    asm volatile("ld.acquire.gpu.u32 %0, [%1];" : "=r"(v) : "l"(p) : "memory");
    return v;
}

__device__ __forceinline__ void red_add_release_u32(unsigned* p, unsigned v) {
    asm volatile("red.add.release.gpu.u32 [%0], %1;" :: "l"(p), "r"(v) : "memory");
}

__device__ __forceinline__ unsigned atom_add_acqrel_u32(unsigned* p, unsigned v) {
    unsigned o;
    asm volatile("atom.add.acq_rel.gpu.u32 %0, [%1], %2;"
                 : "=r"(o) : "l"(p), "r"(v) : "memory");
    return o;
}

__device__ __forceinline__ double ld_acq_f64(const double* p) {
    double v;
    asm volatile("ld.acquire.gpu.f64 %0, [%1];" : "=d"(v) : "l"(p) : "memory");
    return v;
}

__global__ void __launch_bounds__(TPB, 4)
fused_loss_kernel(const float* __restrict__ logits,
                  const float* __restrict__ target,
                  float* __restrict__ out, int out_size)
{
    const int tid  = threadIdx.x;
    const int bid  = blockIdx.x;
    const int lane = tid & 31, warp = tid >> 5;

    __shared__ float s_g2[RPB][WW + 2 * PAD];  // padded, clamp-free window
    __shared__ float s_p[RPB][WW];
    __shared__ float s_red[8][5];

    // worker assignment (never crosses a batch boundary)
    const int wrk   = bid - P1B;                     // 0..511 for workers
    const int wb    = (wrk >= 0) ? (wrk >> 6) : 0;   // batch
    const int widx  = (wrk >= 0) ? (wrk & 63) : 0;
    const int r0    = widx * RPB;                    // row within batch
    const int grow0 = wb * HH + r0;                  // global row

    // row-major pixel mapping for elementwise + EDT phases
    const int rloc = tid >> 6;                       // 0..3
    const int c0   = (tid & 63) * 4;                 // column group

    float acc0 = 0.f, acc1 = 0.f, acc2 = 0.f, acc3 = 0.f, acc4 = 0.f;

    if (bid < P1B) {
        // ========= mask builders: load 32 rows, pack, store, release ========
        int b   = bid >> 3;
        int col = ((bid & 7) << 5) + lane;
        int rc0 = warp << 5;
        const float* tp = target + b * HH * WW + col;

        unsigned mask = 0;
        #pragma unroll
        for (int i = 0; i < 32; i++) {
            float tv = tp[(rc0 + i) * WW];           // 32 independent loads
            if (tv > 0.5f) mask |= (1u << i);
        }
        g_mask[(b * 8 + warp) * WW + col] = mask;    // coalesced
        if (__any_sync(0xffffffffu, mask != 0u) && lane == 0)
            g_nonempty[b] = 1;                       // benign same-value race
        __syncthreads();                             // CTA-wide store ordering
        if (tid == 0) red_add_release_u32(&g_cnt[b], 1u);  // release masks
    } else {
        // ========= workers: elementwise (float4, row-major) =================
        if (tid < PAD) {
            #pragma unroll
            for (int i = 0; i < RPB; i++) {
                s_g2[i][tid] = 1e30f;
                s_g2[i][WW + PAD + tid] = 1e30f;
            }
        }

        const int idx4 = (grow0 + rloc) * WW + c0;
        float4 xv = *reinterpret_cast<const float4*>(logits + idx4);
        float4 tv = *reinterpret_cast<const float4*>(target + idx4);

        float pv[4];
        {
            const float xs[4] = { xv.x, xv.y, xv.z, xv.w };
            const float ts[4] = { tv.x, tv.y, tv.z, tv.w };
            #pragma unroll
            for (int k = 0; k < 4; k++) {
                float x = xs[k];
                float t = fminf(fmaxf(ts[k], 0.0f), 1.0f);
                float th;
                asm("tanh.approx.f32 %0, %1;" : "=f"(th) : "f"(0.5f * x));
                float h = 0.5f * th;                 // sigmoid(x) = 0.5 + h
                float p = fminf(fmaxf(0.5f + h, 1e-6f), 1.0f - 1e-6f);
                float r = 0.5f + fabsf(h);           // sigmoid(|x|)
                float ce = fmaxf(x, 0.0f) - 0.69314718055994531f * __log2f(r)
                         - x * t;
                pv[k] = p;
                acc0 += ce; acc1 += p; acc2 += t; acc3 += p * t;
            }
        }
        *reinterpret_cast<float4*>(&s_p[rloc][c0]) =
            make_float4(pv[0], pv[1], pv[2], pv[3]);

        // ========= acquire this batch's masks (per-thread ld.acquire) =======
        while (ld_acq_u32(&g_cnt[wb]) < 8u) __nanosleep(32);

        // ========= vertical distances (col-major: thread = column tid) ======
        {
            unsigned m[8];
            #pragma unroll
            for (int wp = 0; wp < 8; wp++)
                m[wp] = g_mask[(wb * 8 + wp) * WW + tid];

            int fwdA[RPB], bwdA[RPB];
            {
                int r = r0, w = r >> 5, bit = r & 31;
                int best_lo = -513;
                #pragma unroll
                for (int wp = 0; wp < 8; wp++) {
                    unsigned mm = m[wp];
                    if (wp > w) mm = 0;
                    else if (wp == w) mm &= (0xffffffffu >> (31 - bit));
                    if (mm) best_lo = (wp << 5) + 31 - __clz(mm);
                }
                int f = r - best_lo;
                fwdA[0] = f;
                #pragma unroll
                for (int i = 1; i < RPB; i++) {
                    int rr = r0 + i;
                    f = ((m[rr >> 5] >> (rr & 31)) & 1u) ? 0 : f + 1;
                    fwdA[i] = f;
                }
            }
            {
                int re = r0 + RPB - 1, w = re >> 5, bit = re & 31;
                int best_hi = 768;
                #pragma unroll
                for (int wp = 7; wp >= 0; wp--) {
                    unsigned mm = m[wp];
                    if (wp < w) mm = 0;
                    else if (wp == w) mm &= (0xffffffffu << bit);
                    if (mm) best_hi = (wp << 5) + __ffs(mm) - 1;
                }
                int bw = best_hi - re;
                bwdA[RPB - 1] = bw;
                #pragma unroll
                for (int i = RPB - 2; i >= 0; i--) {
                    int rr = r0 + i;
                    bw = ((m[rr >> 5] >> (rr & 31)) & 1u) ? 0 : bw + 1;
                    bwdA[i] = bw;
                }
            }
            #pragma unroll
            for (int i = 0; i < RPB; i++) {
                int g = min(fwdA[i], bwdA[i]);
                s_g2[i][PAD + tid] = (float)(g * g);
            }
        }
        __syncthreads();

        // ========= EDT (row-major: thread = 4 cols of 1 row) ================
        if (g_nonempty[wb]) {
            const float* row = &s_g2[rloc][0];
            float v[12];
            {
                const float4 a = *reinterpret_cast<const float4*>(row + PAD + c0 - 4);
                const float4 b = *reinterpret_cast<const float4*>(row + PAD + c0);
                const float4 c = *reinterpret_cast<const float4*>(row + PAD + c0 + 4);
                v[0]=a.x; v[1]=a.y; v[2]=a.z; v[3]=a.w;
                v[4]=b.x; v[5]=b.y; v[6]=b.z; v[7]=b.w;
                v[8]=c.x; v[9]=c.y; v[10]=c.z; v[11]=c.w;
            }
            float best[4], bmax = 0.0f;
            #pragma unroll
            for (int k = 0; k < 4; k++) {
                float bk = v[4 + k];
                #pragma unroll
                for (int off = 1; off <= 4; off++) {
                    bk = fminf(bk, fminf(v[4 + k - off], v[4 + k + off])
                                   + (float)(off * off));
                }
                best[k] = bk;
                bmax = fmaxf(bmax, bk);
            }
            if (__any_sync(0xffffffffu, 25.0f < bmax)) {   // rare wide search
                int off = 5;
                float o2 = 25.0f;
                while (__any_sync(0xffffffffu, o2 < bmax)) {
                    bmax = 0.0f;
                    #pragma unroll
                    for (int k = 0; k < 4; k++) {
                        int cc = c0 + k;
                        int l = cc - off; l = (l < 0) ? 0 : l;
                        int r = cc + off; r = (r > WW - 1) ? WW - 1 : r;
                        best[k] = fminf(best[k],
                                        fminf(row[PAD + l], row[PAD + r]) + o2);
                        bmax = fmaxf(bmax, best[k]);
                    }
                    off++;
                    o2 = (float)(off * off);
                    if (off >= WW) break;
                }
            }
            const float4 pq = *reinterpret_cast<const float4*>(&s_p[rloc][c0]);
            const float pk[4] = { pq.x, pq.y, pq.z, pq.w };
            #pragma unroll
            for (int k = 0; k < 4; k++) {
                float b2 = best[k];
                float dt = (b2 <= 1.0f) ? b2 : sqrt_approx(b2);
                acc4 += pk[k] * dt;
            }
        }
    }

    // ========== block reduce -> 5 double atomics into g_sums ================
    {
        float accs[5] = { acc0, acc1, acc2, acc3, acc4 };
        #pragma unroll
        for (int s = 0; s < 5; s++) {
            float v = warp_sum_f(accs[s]);
            if (lane == 0) s_red[warp][s] = v;
        }
        __syncthreads();
        if (warp < 5) {                  // warps 0..4 reduce one scalar each
            float v = (lane < 8) ? s_red[lane][warp] : 0.0f;
            v = warp_sum_f(v);
            if (lane == 0) atomicAdd(&g_sums[warp], (double)v);
        }
    }
    __syncthreads();

    // ========== completion ticket (acq_rel); last block finalizes ===========
    if (tid == 0) {
        unsigned ticket = atom_add_acqrel_u32(&g_done, 1u);
        if (ticket == GRID - 1) {
            double f0 = ld_acq_f64(&g_sums[0]);
            double f1 = ld_acq_f64(&g_sums[1]);
            double f2 = ld_acq_f64(&g_sums[2]);
            double f3 = ld_acq_f64(&g_sums[3]);
            double f4 = ld_acq_f64(&g_sums[4]);

            const double N = (double)NPIX, S = 1e-6;
            double ce       = f0 / N;
            double dice     = 1.0 - (2.0 * f3 + S) / (f1 + f2 + S);
            double boundary = f4 / N;
            double total    = ce + dice + 0.1 * boundary;

            float vals[4] = { (float)total, (float)ce, (float)dice, (float)boundary };
            for (int i = 0; i < out_size && i < 4; i++) out[i] = vals[i];

            // reset persistent state for next graph replay
            g_done = 0;
            for (int s = 0; s < 5; s++) g_sums[s] = 0.0;
            for (int b = 0; b < BB; b++) { g_nonempty[b] = 0; g_cnt[b] = 0; }
        }
    }
}

extern "C" void kernel_launch(void* const* d_in, const int* in_sizes, int n_in,
                              void* d_out, int out_size) {
    const float* logits = (const float*)d_in[0];
    const float* target = (const float*)d_in[1];
    (void)in_sizes; (void)n_in;
    fused_loss_kernel<<<GRID, TPB>>>(logits, target, (float*)d_out, out_size);
}